// round 4
// baseline (speedup 1.0000x reference)
#include <cuda_runtime.h>
#include <cstdint>

#define BB     256
#define IN_F   1024
#define OUT_F  128
#define KD     16
#define NCOL   (OUT_F * KD)        // 2048
#define OUTW   (IN_F + OUT_F)      // 1152

#define SPLITS 4
#define KSPLIT (IN_F / SPLITS)     // 256
#define BM     64
#define BN     64
#define BKK    32
#define NKT    (KSPLIT / BKK)      // 8

#define B2SPLIT 4
#define B2LEN   (BB / B2SPLIT)     // 64

// exp(-s) == +0.0f exactly for s >= 105 (2^-151 < denormal min); partial L1
// sums are lower bounds, so early-exit on partial >= THRESH is lossless.
#define THRESH 105.0f

// GEMM partials: [SPLITS][256][2048] fp32 = 8 MB
__device__ float d_part[SPLITS * BB * NCOL];

__device__ __forceinline__ unsigned long long addx2(unsigned long long a,
                                                    unsigned long long b) {
    unsigned long long r;
    asm("add.rn.f32x2 %0, %1, %2;" : "=l"(r) : "l"(a), "l"(b));
    return r;
}

__device__ __forceinline__ void cp16(uint32_t smem, const void* gmem) {
    asm volatile("cp.async.cg.shared.global [%0], [%1], 16;"
                 :: "r"(smem), "l"(gmem));
}

// ---------------------------------------------------------------------------
// GEMM via mma.sync m16n8k8 tf32, split-K x4.
// grid (32, 4, 5): z<4 = compute, z==4 = x copy + "-1" init of o_b region.
// ---------------------------------------------------------------------------
__global__ __launch_bounds__(128) void gemm_tf32_kernel(
    const float* __restrict__ A,   // x  [256][1024]
    const float* __restrict__ B,   // t  [1024][2048]
    float* __restrict__ C,         // d_part
    float* __restrict__ out)       // [256][1152]
{
    const int tid = threadIdx.x;

    if (blockIdx.z == SPLITS) {
        const int id = blockIdx.y * gridDim.x + blockIdx.x;  // 0..127
#pragma unroll
        for (int rr = 0; rr < 2; rr++) {
            const int r = id * 2 + rr;
            const float4* src = (const float4*)(A + r * IN_F);
            float4*       dst = (float4*)(out + r * OUTW);
            dst[tid]       = src[tid];
            dst[tid + 128] = src[tid + 128];
            if (tid < 32)
                ((float4*)(out + r * OUTW + IN_F))[tid] =
                    make_float4(-1.f, -1.f, -1.f, -1.f);
        }
        return;
    }

    __shared__ float As[2][BM * 36];
    __shared__ float Bs[2][BKK * 72];

    const int lane = tid & 31;
    const int wid  = tid >> 5;
    const int g    = lane >> 2;
    const int t    = lane & 3;
    const int wm   = (wid >> 1) * 32;
    const int wn   = (wid & 1) * 32;
    const int bm0  = blockIdx.y * BM;
    const int bn0  = blockIdx.x * BN;
    const int koff = blockIdx.z * KSPLIT;

    const int arow = tid >> 3;
    const int acol = (tid & 7) * 4;
    const int brow = tid >> 4;
    const int bcol = (tid & 15) * 4;

    uint32_t as_b[2], bs_b[2];
#pragma unroll
    for (int b = 0; b < 2; b++) {
        as_b[b] = (uint32_t)__cvta_generic_to_shared(&As[b][0]);
        bs_b[b] = (uint32_t)__cvta_generic_to_shared(&Bs[b][0]);
    }

    auto fetch = [&](int buf, int k0) {
#pragma unroll
        for (int i = 0; i < 4; i++)
            cp16(as_b[buf] + (((arow + i * 16) * 36 + acol) << 2),
                 &A[(bm0 + arow + i * 16) * IN_F + k0 + acol]);
#pragma unroll
        for (int i = 0; i < 4; i++)
            cp16(bs_b[buf] + (((brow + i * 8) * 72 + bcol) << 2),
                 &B[(k0 + brow + i * 8) * NCOL + bn0 + bcol]);
        asm volatile("cp.async.commit_group;");
    };

    float acc[2][4][4];
#pragma unroll
    for (int mf = 0; mf < 2; mf++)
#pragma unroll
        for (int nf = 0; nf < 4; nf++)
#pragma unroll
            for (int i = 0; i < 4; i++) acc[mf][nf][i] = 0.0f;

    fetch(0, koff);

#pragma unroll 1
    for (int kt = 0; kt < NKT; kt++) {
        if (kt + 1 < NKT) {
            fetch((kt + 1) & 1, koff + (kt + 1) * BKK);
            asm volatile("cp.async.wait_group 1;");
        } else {
            asm volatile("cp.async.wait_group 0;");
        }
        __syncthreads();
        const int cur = kt & 1;

#pragma unroll
        for (int ks = 0; ks < 4; ks++) {
            const int k = ks * 8;
            uint32_t ua[2][4], ub[4][2];
#pragma unroll
            for (int mf = 0; mf < 2; mf++) {
                const float* ap = &As[cur][(wm + mf * 16) * 36 + k];
                ua[mf][0] = __float_as_uint(ap[g * 36 + t]);
                ua[mf][1] = __float_as_uint(ap[(g + 8) * 36 + t]);
                ua[mf][2] = __float_as_uint(ap[g * 36 + t + 4]);
                ua[mf][3] = __float_as_uint(ap[(g + 8) * 36 + t + 4]);
            }
#pragma unroll
            for (int nf = 0; nf < 4; nf++) {
                const float* bp = &Bs[cur][k * 72 + wn + nf * 8 + g];
                ub[nf][0] = __float_as_uint(bp[t * 72]);
                ub[nf][1] = __float_as_uint(bp[(t + 4) * 72]);
            }
#pragma unroll
            for (int mf = 0; mf < 2; mf++)
#pragma unroll
                for (int nf = 0; nf < 4; nf++) {
                    asm volatile(
                        "mma.sync.aligned.m16n8k8.row.col.f32.tf32.tf32.f32 "
                        "{%0,%1,%2,%3}, {%4,%5,%6,%7}, {%8,%9}, {%0,%1,%2,%3};\n"
                        : "+f"(acc[mf][nf][0]), "+f"(acc[mf][nf][1]),
                          "+f"(acc[mf][nf][2]), "+f"(acc[mf][nf][3])
                        : "r"(ua[mf][0]), "r"(ua[mf][1]),
                          "r"(ua[mf][2]), "r"(ua[mf][3]),
                          "r"(ub[nf][0]), "r"(ub[nf][1]));
                }
        }
        __syncthreads();
    }

    float* Cz = C + blockIdx.z * BB * NCOL;
#pragma unroll
    for (int mf = 0; mf < 2; mf++)
#pragma unroll
        for (int nf = 0; nf < 4; nf++) {
            const int r0 = bm0 + wm + mf * 16 + g;
            const int c0 = bn0 + wn + nf * 8 + t * 2;
            *(float2*)&Cz[r0 * NCOL + c0] =
                make_float2(acc[mf][nf][0], acc[mf][nf][1]);
            *(float2*)&Cz[(r0 + 8) * NCOL + c0] =
                make_float2(acc[mf][nf][2], acc[mf][nf][3]);
        }
}

// ---------------------------------------------------------------------------
// Pairwise exp(-L1): packed f32x2, early-exit after 8 components when the
// partial L1 already forces exp() == 0. grid (128 o, 4 b2-quarter), 256 thr.
// ---------------------------------------------------------------------------
__global__ __launch_bounds__(256) void pair_kernel(
    const float* __restrict__ part, float* __restrict__ out)
{
    __shared__ ulonglong2 sm[B2LEN][4];

    const int o  = blockIdx.x;
    const int s  = blockIdx.y;
    const int b1 = threadIdx.x;

    // sum split-K partials for row (b1, o)
    const ulonglong2* p0 = (const ulonglong2*)(part + b1 * NCOL + o * KD);
    ulonglong2 q[4];
#pragma unroll
    for (int i = 0; i < 4; i++) q[i] = p0[i];
#pragma unroll
    for (int sp = 1; sp < SPLITS; sp++) {
        const ulonglong2* ps =
            (const ulonglong2*)(part + sp * BB * NCOL + b1 * NCOL + o * KD);
#pragma unroll
        for (int i = 0; i < 4; i++) {
            ulonglong2 v = ps[i];
            q[i].x = addx2(q[i].x, v.x);
            q[i].y = addx2(q[i].y, v.y);
        }
    }

    unsigned long long a[8];
#pragma unroll
    for (int i = 0; i < 4; i++) { a[2 * i] = q[i].x; a[2 * i + 1] = q[i].y; }

    // stage negated rows of this block's b2 range
    const unsigned long long SGN = 0x8000000080000000ULL;
    const int lb = b1 - s * B2LEN;
    if ((unsigned)lb < (unsigned)B2LEN) {
#pragma unroll
        for (int i = 0; i < 4; i++)
            sm[lb][i] = make_ulonglong2(a[2 * i] ^ SGN, a[2 * i + 1] ^ SGN);
    }
    __syncthreads();

    const unsigned long long MSK = 0x7FFFFFFF7FFFFFFFULL;
    float tot = 0.0f;
#pragma unroll 2
    for (int b2 = 0; b2 < B2LEN; b2++) {
        // first 8 components
        ulonglong2 c0 = sm[b2][0], c1 = sm[b2][1];
        unsigned long long d0 = addx2(a[0], c0.x) & MSK;
        unsigned long long d1 = addx2(a[1], c0.y) & MSK;
        unsigned long long d2 = addx2(a[2], c1.x) & MSK;
        unsigned long long d3 = addx2(a[3], c1.y) & MSK;
        unsigned long long f  = addx2(addx2(d0, d1), addx2(d2, d3));
        uint32_t flo, fhi;
        asm("mov.b64 {%0,%1}, %2;" : "=r"(flo), "=r"(fhi) : "l"(f));
        float s8 = __uint_as_float(flo) + __uint_as_float(fhi);

        if (s8 < THRESH) {   // otherwise exp(-total) == +0 exactly
            ulonglong2 c2 = sm[b2][2], c3 = sm[b2][3];
            unsigned long long d4 = addx2(a[4], c2.x) & MSK;
            unsigned long long d5 = addx2(a[5], c2.y) & MSK;
            unsigned long long d6 = addx2(a[6], c3.x) & MSK;
            unsigned long long d7 = addx2(a[7], c3.y) & MSK;
            unsigned long long g  = addx2(addx2(d4, d5), addx2(d6, d7));
            uint32_t glo, ghi;
            asm("mov.b64 {%0,%1}, %2;" : "=r"(glo), "=r"(ghi) : "l"(g));
            float s16 = s8 + __uint_as_float(glo) + __uint_as_float(ghi);
            tot += __expf(-s16);
        }
    }

    atomicAdd(&out[b1 * OUTW + IN_F + o], tot);
}

extern "C" void kernel_launch(void* const* d_in, const int* in_sizes, int n_in,
                              void* d_out, int out_size)
{
    const float* x = (const float*)d_in[0];     // [256][1024]
    const float* t = (const float*)d_in[1];     // [1024][2048]
    float* out = (float*)d_out;                 // [256][1152]

    float* part;
    cudaGetSymbolAddress((void**)&part, d_part);

    dim3 ggrid(NCOL / BN, BB / BM, SPLITS + 1);  // (32, 4, 5)
    gemm_tf32_kernel<<<ggrid, 128>>>(x, t, part, out);
    pair_kernel<<<dim3(OUT_F, B2SPLIT), 256>>>(part, out);
}

// round 5
// speedup vs baseline: 1.1396x; 1.1396x over previous
#include <cuda_runtime.h>
#include <cstdint>

#define BB     256
#define IN_F   1024
#define OUT_F  128
#define KD     16
#define NCOL   (OUT_F * KD)        // 2048
#define OUTW   (IN_F + OUT_F)      // 1152

#define SPLITS 4
#define KSPLIT (IN_F / SPLITS)     // 256
#define PSZ    (BB * NCOL)         // elems per split partial
#define BM     64
#define BN     64
#define BKK    32
#define NKT    (KSPLIT / BKK)      // 8

#define B2SPLIT 2
#define B2LEN   (BB / B2SPLIT)     // 128

// exp(-s) == +0.0f exactly for s >= 105; partial L1 sums are lower bounds,
// so early-exit on partial >= THRESH is lossless.
#define THRESH 105.0f

// GEMM partials, TRANSPOSED layout: [sp][o][b][k] fp32 = 8 MB
__device__ float d_part[SPLITS * PSZ];

__device__ __forceinline__ unsigned long long addx2(unsigned long long a,
                                                    unsigned long long b) {
    unsigned long long r;
    asm("add.rn.f32x2 %0, %1, %2;" : "=l"(r) : "l"(a), "l"(b));
    return r;
}

__device__ __forceinline__ void cp16(uint32_t smem, const void* gmem) {
    asm volatile("cp.async.cg.shared.global [%0], [%1], 16;"
                 :: "r"(smem), "l"(gmem));
}

// ---------------------------------------------------------------------------
// GEMM via mma.sync m16n8k8 tf32, split-K x4, epilogue writes m transposed
// as [o][b][k]. grid (32, 4, 5): z<4 compute, z==4 x-copy + "-1" init.
// ---------------------------------------------------------------------------
__global__ __launch_bounds__(128) void gemm_tf32_kernel(
    const float* __restrict__ A,   // x  [256][1024]
    const float* __restrict__ B,   // t  [1024][2048]
    float* __restrict__ C,         // d_part
    float* __restrict__ out)       // [256][1152]
{
    const int tid = threadIdx.x;

    if (blockIdx.z == SPLITS) {
        const int id = blockIdx.y * gridDim.x + blockIdx.x;  // 0..127
#pragma unroll
        for (int rr = 0; rr < 2; rr++) {
            const int r = id * 2 + rr;
            const float4* src = (const float4*)(A + r * IN_F);
            float4*       dst = (float4*)(out + r * OUTW);
            dst[tid]       = src[tid];
            dst[tid + 128] = src[tid + 128];
            if (tid < 32)
                ((float4*)(out + r * OUTW + IN_F))[tid] =
                    make_float4(-1.f, -1.f, -1.f, -1.f);
        }
        return;
    }

    __shared__ float As[2][BM * 36];
    __shared__ float Bs[2][BKK * 72];

    const int lane = tid & 31;
    const int wid  = tid >> 5;
    const int g    = lane >> 2;
    const int t    = lane & 3;
    const int wm   = (wid >> 1) * 32;
    const int wn   = (wid & 1) * 32;
    const int bm0  = blockIdx.y * BM;
    const int bn0  = blockIdx.x * BN;
    const int koff = blockIdx.z * KSPLIT;

    const int arow = tid >> 3;
    const int acol = (tid & 7) * 4;
    const int brow = tid >> 4;
    const int bcol = (tid & 15) * 4;

    uint32_t as_b[2], bs_b[2];
#pragma unroll
    for (int b = 0; b < 2; b++) {
        as_b[b] = (uint32_t)__cvta_generic_to_shared(&As[b][0]);
        bs_b[b] = (uint32_t)__cvta_generic_to_shared(&Bs[b][0]);
    }

    auto fetch = [&](int buf, int k0) {
#pragma unroll
        for (int i = 0; i < 4; i++)
            cp16(as_b[buf] + (((arow + i * 16) * 36 + acol) << 2),
                 &A[(bm0 + arow + i * 16) * IN_F + k0 + acol]);
#pragma unroll
        for (int i = 0; i < 4; i++)
            cp16(bs_b[buf] + (((brow + i * 8) * 72 + bcol) << 2),
                 &B[(k0 + brow + i * 8) * NCOL + bn0 + bcol]);
        asm volatile("cp.async.commit_group;");
    };

    float acc[2][4][4];
#pragma unroll
    for (int mf = 0; mf < 2; mf++)
#pragma unroll
        for (int nf = 0; nf < 4; nf++)
#pragma unroll
            for (int i = 0; i < 4; i++) acc[mf][nf][i] = 0.0f;

    fetch(0, koff);

#pragma unroll 1
    for (int kt = 0; kt < NKT; kt++) {
        if (kt + 1 < NKT) {
            fetch((kt + 1) & 1, koff + (kt + 1) * BKK);
            asm volatile("cp.async.wait_group 1;");
        } else {
            asm volatile("cp.async.wait_group 0;");
        }
        __syncthreads();
        const int cur = kt & 1;

#pragma unroll
        for (int ks = 0; ks < 4; ks++) {
            const int k = ks * 8;
            uint32_t ua[2][4], ub[4][2];
#pragma unroll
            for (int mf = 0; mf < 2; mf++) {
                const float* ap = &As[cur][(wm + mf * 16) * 36 + k];
                ua[mf][0] = __float_as_uint(ap[g * 36 + t]);
                ua[mf][1] = __float_as_uint(ap[(g + 8) * 36 + t]);
                ua[mf][2] = __float_as_uint(ap[g * 36 + t + 4]);
                ua[mf][3] = __float_as_uint(ap[(g + 8) * 36 + t + 4]);
            }
#pragma unroll
            for (int nf = 0; nf < 4; nf++) {
                const float* bp = &Bs[cur][k * 72 + wn + nf * 8 + g];
                ub[nf][0] = __float_as_uint(bp[t * 72]);
                ub[nf][1] = __float_as_uint(bp[(t + 4) * 72]);
            }
#pragma unroll
            for (int mf = 0; mf < 2; mf++)
#pragma unroll
                for (int nf = 0; nf < 4; nf++) {
                    asm volatile(
                        "mma.sync.aligned.m16n8k8.row.col.f32.tf32.tf32.f32 "
                        "{%0,%1,%2,%3}, {%4,%5,%6,%7}, {%8,%9}, {%0,%1,%2,%3};\n"
                        : "+f"(acc[mf][nf][0]), "+f"(acc[mf][nf][1]),
                          "+f"(acc[mf][nf][2]), "+f"(acc[mf][nf][3])
                        : "r"(ua[mf][0]), "r"(ua[mf][1]),
                          "r"(ua[mf][2]), "r"(ua[mf][3]),
                          "r"(ub[nf][0]), "r"(ub[nf][1]));
                }
        }
        __syncthreads();
    }

    // epilogue: write transposed m[o][b][k];  o = col>>4, k = col&15
    float* Cz = C + blockIdx.z * PSZ;
#pragma unroll
    for (int mf = 0; mf < 2; mf++)
#pragma unroll
        for (int nf = 0; nf < 4; nf++) {
            const int r0 = bm0 + wm + mf * 16 + g;
            const int o  = ((bn0 + wn) >> 4) + (nf >> 1);
            const int k  = ((nf & 1) << 3) + t * 2;
            float* p = Cz + o * (BB * KD) + k;
            *(float2*)&p[r0 * KD] =
                make_float2(acc[mf][nf][0], acc[mf][nf][1]);
            *(float2*)&p[(r0 + 8) * KD] =
                make_float2(acc[mf][nf][2], acc[mf][nf][3]);
        }
}

// ---------------------------------------------------------------------------
// Pairwise exp(-L1): packed f32x2 + 8-comp early exit.
// grid (128 o, 2 b2-halves), 256 thr. Transposed m -> coalesced preamble
// (lane stride 64B). b2 rows staged negated in smem from thread regs.
// ---------------------------------------------------------------------------
__global__ __launch_bounds__(256) void pair_kernel(
    const float* __restrict__ part, float* __restrict__ out)
{
    __shared__ ulonglong2 sm[B2LEN][4];

    const int o  = blockIdx.x;
    const int s  = blockIdx.y;
    const int b1 = threadIdx.x;

    // coalesced: row = part + sp*PSZ + o*4096 + b1*16
    const size_t roff = (size_t)o * (BB * KD) + (size_t)b1 * KD;
    ulonglong2 q[4];
    {
        const ulonglong2* p0 = (const ulonglong2*)(part + roff);
#pragma unroll
        for (int i = 0; i < 4; i++) q[i] = p0[i];
    }
#pragma unroll
    for (int sp = 1; sp < SPLITS; sp++) {
        const ulonglong2* ps = (const ulonglong2*)(part + sp * PSZ + roff);
#pragma unroll
        for (int i = 0; i < 4; i++) {
            ulonglong2 v = ps[i];
            q[i].x = addx2(q[i].x, v.x);
            q[i].y = addx2(q[i].y, v.y);
        }
    }

    unsigned long long a[8];
#pragma unroll
    for (int i = 0; i < 4; i++) { a[2 * i] = q[i].x; a[2 * i + 1] = q[i].y; }

    const unsigned long long SGN = 0x8000000080000000ULL;
    const int lb = b1 - s * B2LEN;
    if ((unsigned)lb < (unsigned)B2LEN) {
#pragma unroll
        for (int i = 0; i < 4; i++)
            sm[lb][i] = make_ulonglong2(a[2 * i] ^ SGN, a[2 * i + 1] ^ SGN);
    }
    __syncthreads();

    const unsigned long long MSK = 0x7FFFFFFF7FFFFFFFULL;
    float tot = 0.0f;
#pragma unroll 2
    for (int b2 = 0; b2 < B2LEN; b2++) {
        ulonglong2 c0 = sm[b2][0], c1 = sm[b2][1];
        unsigned long long d0 = addx2(a[0], c0.x) & MSK;
        unsigned long long d1 = addx2(a[1], c0.y) & MSK;
        unsigned long long d2 = addx2(a[2], c1.x) & MSK;
        unsigned long long d3 = addx2(a[3], c1.y) & MSK;
        unsigned long long f  = addx2(addx2(d0, d1), addx2(d2, d3));
        uint32_t flo, fhi;
        asm("mov.b64 {%0,%1}, %2;" : "=r"(flo), "=r"(fhi) : "l"(f));
        float s8 = __uint_as_float(flo) + __uint_as_float(fhi);

        if (s8 < THRESH) {   // otherwise exp(-total) == +0 exactly
            ulonglong2 c2 = sm[b2][2], c3 = sm[b2][3];
            unsigned long long d4 = addx2(a[4], c2.x) & MSK;
            unsigned long long d5 = addx2(a[5], c2.y) & MSK;
            unsigned long long d6 = addx2(a[6], c3.x) & MSK;
            unsigned long long d7 = addx2(a[7], c3.y) & MSK;
            unsigned long long g  = addx2(addx2(d4, d5), addx2(d6, d7));
            uint32_t glo, ghi;
            asm("mov.b64 {%0,%1}, %2;" : "=r"(glo), "=r"(ghi) : "l"(g));
            float s16 = s8 + __uint_as_float(glo) + __uint_as_float(ghi);
            tot += __expf(-s16);
        }
    }

    atomicAdd(&out[b1 * OUTW + IN_F + o], tot);
}

extern "C" void kernel_launch(void* const* d_in, const int* in_sizes, int n_in,
                              void* d_out, int out_size)
{
    const float* x = (const float*)d_in[0];     // [256][1024]
    const float* t = (const float*)d_in[1];     // [1024][2048]
    float* out = (float*)d_out;                 // [256][1152]

    float* part;
    cudaGetSymbolAddress((void**)&part, d_part);

    dim3 ggrid(NCOL / BN, BB / BM, SPLITS + 1);  // (32, 4, 5)
    gemm_tf32_kernel<<<ggrid, 128>>>(x, t, part, out);
    pair_kernel<<<dim3(OUT_F, B2SPLIT), 256>>>(part, out);
}

// round 6
// speedup vs baseline: 1.2997x; 1.1405x over previous
#include <cuda_runtime.h>
#include <cstdint>

#define BB     256
#define IN_F   1024
#define OUT_F  128
#define KD     16
#define NCOL   (OUT_F * KD)        // 2048
#define OUTW   (IN_F + OUT_F)      // 1152

#define SPLITS 4
#define KSPLIT (IN_F / SPLITS)     // 256
#define PSZ    (BB * NCOL)
#define BM     64
#define BN     64
#define BKK    32
#define NKT    (KSPLIT / BKK)      // 8

#define B2SPLIT 2                  // b2 parity classes
#define NJ      (BB / B2SPLIT)     // 128 strided b2 per block

// exp(-s) == +0.0f exactly for s >= 105; partial L1 sums are lower bounds,
// so screening on partial >= THRESH is lossless.
#define THRESH 105.0f

// GEMM partials, transposed layout: [sp][o][b][k] fp32 = 8 MB
__device__ float d_part[SPLITS * PSZ];

__device__ __forceinline__ unsigned long long addx2(unsigned long long a,
                                                    unsigned long long b) {
    unsigned long long r;
    asm("add.rn.f32x2 %0, %1, %2;" : "=l"(r) : "l"(a), "l"(b));
    return r;
}

__device__ __forceinline__ void cp16(uint32_t smem, const void* gmem) {
    asm volatile("cp.async.cg.shared.global [%0], [%1], 16;"
                 :: "r"(smem), "l"(gmem));
}

// ---------------------------------------------------------------------------
// GEMM via mma.sync m16n8k8 tf32, split-K x4, transposed epilogue [o][b][k].
// grid (32, 4, 5): z<4 compute, z==4 x-copy + ZERO init of o_b region.
// ---------------------------------------------------------------------------
__global__ __launch_bounds__(128) void gemm_tf32_kernel(
    const float* __restrict__ A,
    const float* __restrict__ B,
    float* __restrict__ C,
    float* __restrict__ out)
{
    const int tid = threadIdx.x;

    if (blockIdx.z == SPLITS) {
        const int id = blockIdx.y * gridDim.x + blockIdx.x;  // 0..127
#pragma unroll
        for (int rr = 0; rr < 2; rr++) {
            const int r = id * 2 + rr;
            const float4* src = (const float4*)(A + r * IN_F);
            float4*       dst = (float4*)(out + r * OUTW);
            dst[tid]       = src[tid];
            dst[tid + 128] = src[tid + 128];
            if (tid < 32)   // triangle scheme: diagonal never computed -> 0
                ((float4*)(out + r * OUTW + IN_F))[tid] =
                    make_float4(0.f, 0.f, 0.f, 0.f);
        }
        return;
    }

    __shared__ float As[2][BM * 36];
    __shared__ float Bs[2][BKK * 72];

    const int lane = tid & 31;
    const int wid  = tid >> 5;
    const int g    = lane >> 2;
    const int t    = lane & 3;
    const int wm   = (wid >> 1) * 32;
    const int wn   = (wid & 1) * 32;
    const int bm0  = blockIdx.y * BM;
    const int bn0  = blockIdx.x * BN;
    const int koff = blockIdx.z * KSPLIT;

    const int arow = tid >> 3;
    const int acol = (tid & 7) * 4;
    const int brow = tid >> 4;
    const int bcol = (tid & 15) * 4;

    uint32_t as_b[2], bs_b[2];
#pragma unroll
    for (int b = 0; b < 2; b++) {
        as_b[b] = (uint32_t)__cvta_generic_to_shared(&As[b][0]);
        bs_b[b] = (uint32_t)__cvta_generic_to_shared(&Bs[b][0]);
    }

    auto fetch = [&](int buf, int k0) {
#pragma unroll
        for (int i = 0; i < 4; i++)
            cp16(as_b[buf] + (((arow + i * 16) * 36 + acol) << 2),
                 &A[(bm0 + arow + i * 16) * IN_F + k0 + acol]);
#pragma unroll
        for (int i = 0; i < 4; i++)
            cp16(bs_b[buf] + (((brow + i * 8) * 72 + bcol) << 2),
                 &B[(k0 + brow + i * 8) * NCOL + bn0 + bcol]);
        asm volatile("cp.async.commit_group;");
    };

    float acc[2][4][4];
#pragma unroll
    for (int mf = 0; mf < 2; mf++)
#pragma unroll
        for (int nf = 0; nf < 4; nf++)
#pragma unroll
            for (int i = 0; i < 4; i++) acc[mf][nf][i] = 0.0f;

    fetch(0, koff);

#pragma unroll 1
    for (int kt = 0; kt < NKT; kt++) {
        if (kt + 1 < NKT) {
            fetch((kt + 1) & 1, koff + (kt + 1) * BKK);
            asm volatile("cp.async.wait_group 1;");
        } else {
            asm volatile("cp.async.wait_group 0;");
        }
        __syncthreads();
        const int cur = kt & 1;

#pragma unroll
        for (int ks = 0; ks < 4; ks++) {
            const int k = ks * 8;
            uint32_t ua[2][4], ub[4][2];
#pragma unroll
            for (int mf = 0; mf < 2; mf++) {
                const float* ap = &As[cur][(wm + mf * 16) * 36 + k];
                ua[mf][0] = __float_as_uint(ap[g * 36 + t]);
                ua[mf][1] = __float_as_uint(ap[(g + 8) * 36 + t]);
                ua[mf][2] = __float_as_uint(ap[g * 36 + t + 4]);
                ua[mf][3] = __float_as_uint(ap[(g + 8) * 36 + t + 4]);
            }
#pragma unroll
            for (int nf = 0; nf < 4; nf++) {
                const float* bp = &Bs[cur][k * 72 + wn + nf * 8 + g];
                ub[nf][0] = __float_as_uint(bp[t * 72]);
                ub[nf][1] = __float_as_uint(bp[(t + 4) * 72]);
            }
#pragma unroll
            for (int mf = 0; mf < 2; mf++)
#pragma unroll
                for (int nf = 0; nf < 4; nf++) {
                    asm volatile(
                        "mma.sync.aligned.m16n8k8.row.col.f32.tf32.tf32.f32 "
                        "{%0,%1,%2,%3}, {%4,%5,%6,%7}, {%8,%9}, {%0,%1,%2,%3};\n"
                        : "+f"(acc[mf][nf][0]), "+f"(acc[mf][nf][1]),
                          "+f"(acc[mf][nf][2]), "+f"(acc[mf][nf][3])
                        : "r"(ua[mf][0]), "r"(ua[mf][1]),
                          "r"(ua[mf][2]), "r"(ua[mf][3]),
                          "r"(ub[nf][0]), "r"(ub[nf][1]));
                }
        }
        __syncthreads();
    }

    float* Cz = C + blockIdx.z * PSZ;
#pragma unroll
    for (int mf = 0; mf < 2; mf++)
#pragma unroll
        for (int nf = 0; nf < 4; nf++) {
            const int r0 = bm0 + wm + mf * 16 + g;
            const int o  = ((bn0 + wn) >> 4) + (nf >> 1);
            const int k  = ((nf & 1) << 3) + t * 2;
            float* p = Cz + o * (BB * KD) + k;
            *(float2*)&p[r0 * KD] =
                make_float2(acc[mf][nf][0], acc[mf][nf][1]);
            *(float2*)&p[(r0 + 8) * KD] =
                make_float2(acc[mf][nf][2], acc[mf][nf][3]);
        }
}

// ---------------------------------------------------------------------------
// Pairwise exp(-L1), UPPER TRIANGLE only (b2 > b1), each hit credited to
// both sides. b2 = s + 2j strided; warp w skips j below its range.
// Packed f32x2 + 8-comp lossless screen; unroll x4 for ILP.
// grid (128 o, 2 parity), 256 threads.
// ---------------------------------------------------------------------------
__global__ __launch_bounds__(256) void pair_kernel(
    const float* __restrict__ part, float* __restrict__ out)
{
    __shared__ ulonglong2 sm[NJ][4];

    const int o  = blockIdx.x;
    const int s  = blockIdx.y;      // b2 parity
    const int b1 = threadIdx.x;

    // sum split-K partials for row (o, b1): coalesced (lane stride 64B)
    const size_t roff = (size_t)o * (BB * KD) + (size_t)b1 * KD;
    ulonglong2 q[4];
    {
        const ulonglong2* p0 = (const ulonglong2*)(part + roff);
#pragma unroll
        for (int i = 0; i < 4; i++) q[i] = p0[i];
    }
#pragma unroll
    for (int sp = 1; sp < SPLITS; sp++) {
        const ulonglong2* ps = (const ulonglong2*)(part + sp * PSZ + roff);
#pragma unroll
        for (int i = 0; i < 4; i++) {
            ulonglong2 v = ps[i];
            q[i].x = addx2(q[i].x, v.x);
            q[i].y = addx2(q[i].y, v.y);
        }
    }

    unsigned long long a[8];
#pragma unroll
    for (int i = 0; i < 4; i++) { a[2 * i] = q[i].x; a[2 * i + 1] = q[i].y; }

    // stage negated rows for b2 = s + 2j
    const unsigned long long SGN = 0x8000000080000000ULL;
    if (((b1 - s) & 1) == 0) {
        const int lb = (b1 - s) >> 1;          // 0..127
#pragma unroll
        for (int i = 0; i < 4; i++)
            sm[lb][i] = make_ulonglong2(a[2 * i] ^ SGN, a[2 * i + 1] ^ SGN);
    }
    __syncthreads();

    const unsigned long long MSK = 0x7FFFFFFF7FFFFFFFULL;
    float* ob = out + IN_F + o;
    float tot = 0.0f;

    // warp-uniform start: first j where some lane has b2 > b1
    const int w  = b1 >> 5;
    const int jw = (((w << 5) + 2 - s) >> 1) & ~3;   // aligned to 4

    auto body = [&](int j) {
        const int b2 = (j << 1) + s;
        ulonglong2 c0 = sm[j][0], c1 = sm[j][1];
        unsigned long long d0 = addx2(a[0], c0.x) & MSK;
        unsigned long long d1 = addx2(a[1], c0.y) & MSK;
        unsigned long long d2 = addx2(a[2], c1.x) & MSK;
        unsigned long long d3 = addx2(a[3], c1.y) & MSK;
        unsigned long long f  = addx2(addx2(d0, d1), addx2(d2, d3));
        uint32_t flo, fhi;
        asm("mov.b64 {%0,%1}, %2;" : "=r"(flo), "=r"(fhi) : "l"(f));
        float s8 = __uint_as_float(flo) + __uint_as_float(fhi);

        if (b2 > b1 && s8 < THRESH) {          // else contribution is +0 exactly
            ulonglong2 c2 = sm[j][2], c3 = sm[j][3];
            unsigned long long d4 = addx2(a[4], c2.x) & MSK;
            unsigned long long d5 = addx2(a[5], c2.y) & MSK;
            unsigned long long d6 = addx2(a[6], c3.x) & MSK;
            unsigned long long d7 = addx2(a[7], c3.y) & MSK;
            unsigned long long g  = addx2(addx2(d4, d5), addx2(d6, d7));
            uint32_t glo, ghi;
            asm("mov.b64 {%0,%1}, %2;" : "=r"(glo), "=r"(ghi) : "l"(g));
            float s16 = s8 + __uint_as_float(glo) + __uint_as_float(ghi);
            float e = __expf(-s16);
            tot += e;
            if (e != 0.0f)                     // credit the partner side
                atomicAdd(&ob[(size_t)b2 * OUTW], e);
        }
    };

#pragma unroll 1
    for (int j = jw; j < NJ; j += 4) {
        body(j); body(j + 1); body(j + 2); body(j + 3);
    }

    if (tot != 0.0f)
        atomicAdd(&ob[(size_t)b1 * OUTW], tot);
}

extern "C" void kernel_launch(void* const* d_in, const int* in_sizes, int n_in,
                              void* d_out, int out_size)
{
    const float* x = (const float*)d_in[0];     // [256][1024]
    const float* t = (const float*)d_in[1];     // [1024][2048]
    float* out = (float*)d_out;                 // [256][1152]

    float* part;
    cudaGetSymbolAddress((void**)&part, d_part);

    dim3 ggrid(NCOL / BN, BB / BM, SPLITS + 1);  // (32, 4, 5)
    gemm_tf32_kernel<<<ggrid, 128>>>(x, t, part, out);
    pair_kernel<<<dim3(OUT_F, B2SPLIT), 256>>>(part, out);
}

// round 7
// speedup vs baseline: 1.3979x; 1.0756x over previous
#include <cuda_runtime.h>
#include <cstdint>

#define BB     256
#define IN_F   1024
#define OUT_F  128
#define KD     16
#define NCOL   (OUT_F * KD)        // 2048
#define OUTW   (IN_F + OUT_F)      // 1152

#define SPLITS 4
#define KSPLIT (IN_F / SPLITS)     // 256
#define PSZ    (BB * NCOL)
#define BM     64
#define BN     64
#define BKK    32
#define NKT    (KSPLIT / BKK)      // 8

// exp(-s) == +0.0f exactly for s >= 105; partial L1 sums are lower bounds,
// so screening on partial >= THRESH is lossless.
#define THRESH 105.0f

// GEMM partials, transposed layout: [sp][o][b][k] fp32 = 8 MB
__device__ float d_part[SPLITS * PSZ];

__device__ __forceinline__ unsigned long long addx2(unsigned long long a,
                                                    unsigned long long b) {
    unsigned long long r;
    asm("add.rn.f32x2 %0, %1, %2;" : "=l"(r) : "l"(a), "l"(b));
    return r;
}

__device__ __forceinline__ void cp16(uint32_t smem, const void* gmem) {
    asm volatile("cp.async.cg.shared.global [%0], [%1], 16;"
                 :: "r"(smem), "l"(gmem));
}

// ---------------------------------------------------------------------------
// GEMM via mma.sync m16n8k8 tf32, split-K x4, transposed epilogue [o][b][k].
// grid (32, 4, 5): z<4 compute, z==4 x-copy + ZERO init of o_b region.
// ---------------------------------------------------------------------------
__global__ __launch_bounds__(128) void gemm_tf32_kernel(
    const float* __restrict__ A,
    const float* __restrict__ B,
    float* __restrict__ C,
    float* __restrict__ out)
{
    const int tid = threadIdx.x;

    if (blockIdx.z == SPLITS) {
        const int id = blockIdx.y * gridDim.x + blockIdx.x;  // 0..127
#pragma unroll
        for (int rr = 0; rr < 2; rr++) {
            const int r = id * 2 + rr;
            const float4* src = (const float4*)(A + r * IN_F);
            float4*       dst = (float4*)(out + r * OUTW);
            dst[tid]       = src[tid];
            dst[tid + 128] = src[tid + 128];
            if (tid < 32)   // diagonal never computed -> 0
                ((float4*)(out + r * OUTW + IN_F))[tid] =
                    make_float4(0.f, 0.f, 0.f, 0.f);
        }
        return;
    }

    __shared__ float As[2][BM * 36];
    __shared__ float Bs[2][BKK * 72];

    const int lane = tid & 31;
    const int wid  = tid >> 5;
    const int g    = lane >> 2;
    const int t    = lane & 3;
    const int wm   = (wid >> 1) * 32;
    const int wn   = (wid & 1) * 32;
    const int bm0  = blockIdx.y * BM;
    const int bn0  = blockIdx.x * BN;
    const int koff = blockIdx.z * KSPLIT;

    const int arow = tid >> 3;
    const int acol = (tid & 7) * 4;
    const int brow = tid >> 4;
    const int bcol = (tid & 15) * 4;

    uint32_t as_b[2], bs_b[2];
#pragma unroll
    for (int b = 0; b < 2; b++) {
        as_b[b] = (uint32_t)__cvta_generic_to_shared(&As[b][0]);
        bs_b[b] = (uint32_t)__cvta_generic_to_shared(&Bs[b][0]);
    }

    auto fetch = [&](int buf, int k0) {
#pragma unroll
        for (int i = 0; i < 4; i++)
            cp16(as_b[buf] + (((arow + i * 16) * 36 + acol) << 2),
                 &A[(bm0 + arow + i * 16) * IN_F + k0 + acol]);
#pragma unroll
        for (int i = 0; i < 4; i++)
            cp16(bs_b[buf] + (((brow + i * 8) * 72 + bcol) << 2),
                 &B[(k0 + brow + i * 8) * NCOL + bn0 + bcol]);
        asm volatile("cp.async.commit_group;");
    };

    float acc[2][4][4];
#pragma unroll
    for (int mf = 0; mf < 2; mf++)
#pragma unroll
        for (int nf = 0; nf < 4; nf++)
#pragma unroll
            for (int i = 0; i < 4; i++) acc[mf][nf][i] = 0.0f;

    fetch(0, koff);

#pragma unroll 1
    for (int kt = 0; kt < NKT; kt++) {
        if (kt + 1 < NKT) {
            fetch((kt + 1) & 1, koff + (kt + 1) * BKK);
            asm volatile("cp.async.wait_group 1;");
        } else {
            asm volatile("cp.async.wait_group 0;");
        }
        __syncthreads();
        const int cur = kt & 1;

#pragma unroll
        for (int ks = 0; ks < 4; ks++) {
            const int k = ks * 8;
            uint32_t ua[2][4], ub[4][2];
#pragma unroll
            for (int mf = 0; mf < 2; mf++) {
                const float* ap = &As[cur][(wm + mf * 16) * 36 + k];
                ua[mf][0] = __float_as_uint(ap[g * 36 + t]);
                ua[mf][1] = __float_as_uint(ap[(g + 8) * 36 + t]);
                ua[mf][2] = __float_as_uint(ap[g * 36 + t + 4]);
                ua[mf][3] = __float_as_uint(ap[(g + 8) * 36 + t + 4]);
            }
#pragma unroll
            for (int nf = 0; nf < 4; nf++) {
                const float* bp = &Bs[cur][k * 72 + wn + nf * 8 + g];
                ub[nf][0] = __float_as_uint(bp[t * 72]);
                ub[nf][1] = __float_as_uint(bp[(t + 4) * 72]);
            }
#pragma unroll
            for (int mf = 0; mf < 2; mf++)
#pragma unroll
                for (int nf = 0; nf < 4; nf++) {
                    asm volatile(
                        "mma.sync.aligned.m16n8k8.row.col.f32.tf32.tf32.f32 "
                        "{%0,%1,%2,%3}, {%4,%5,%6,%7}, {%8,%9}, {%0,%1,%2,%3};\n"
                        : "+f"(acc[mf][nf][0]), "+f"(acc[mf][nf][1]),
                          "+f"(acc[mf][nf][2]), "+f"(acc[mf][nf][3])
                        : "r"(ua[mf][0]), "r"(ua[mf][1]),
                          "r"(ua[mf][2]), "r"(ua[mf][3]),
                          "r"(ub[nf][0]), "r"(ub[nf][1]));
                }
        }
        __syncthreads();
    }

    float* Cz = C + blockIdx.z * PSZ;
#pragma unroll
    for (int mf = 0; mf < 2; mf++)
#pragma unroll
        for (int nf = 0; nf < 4; nf++) {
            const int r0 = bm0 + wm + mf * 16 + g;
            const int o  = ((bn0 + wn) >> 4) + (nf >> 1);
            const int k  = ((nf & 1) << 3) + t * 2;
            float* p = Cz + o * (BB * KD) + k;
            *(float2*)&p[r0 * KD] =
                make_float2(acc[mf][nf][0], acc[mf][nf][1]);
            *(float2*)&p[(r0 + 8) * KD] =
                make_float2(acc[mf][nf][2], acc[mf][nf][3]);
        }
}

// ---------------------------------------------------------------------------
// Pairwise exp(-L1), BALANCED cyclic triangle: thread b1 handles partners
// b2=(b1+t)&255 for t in its block's range; every unordered pair computed
// exactly once (t=128 guarded by b1<128) and credited to both sides.
// Chunk-major smem [chunk][b] -> conflict-free gather at per-lane b2.
// grid (128 o, 2 t-halves), 256 threads; each thread: 63/64 + peel iters.
// ---------------------------------------------------------------------------
__global__ __launch_bounds__(256) void pair_kernel(
    const float* __restrict__ part, float* __restrict__ out)
{
    __shared__ ulonglong2 sm2[4][BB];   // [chunk][b], negated rows, 16 KB

    const int o  = blockIdx.x;
    const int s  = blockIdx.y;          // t-half selector
    const int b1 = threadIdx.x;

    // sum split-K partials for row (o, b1): coalesced (lane stride 64B)
    const size_t roff = (size_t)o * (BB * KD) + (size_t)b1 * KD;
    ulonglong2 q[4];
    {
        const ulonglong2* p0 = (const ulonglong2*)(part + roff);
#pragma unroll
        for (int i = 0; i < 4; i++) q[i] = p0[i];
    }
#pragma unroll
    for (int sp = 1; sp < SPLITS; sp++) {
        const ulonglong2* ps = (const ulonglong2*)(part + sp * PSZ + roff);
#pragma unroll
        for (int i = 0; i < 4; i++) {
            ulonglong2 v = ps[i];
            q[i].x = addx2(q[i].x, v.x);
            q[i].y = addx2(q[i].y, v.y);
        }
    }

    unsigned long long a[8];
#pragma unroll
    for (int i = 0; i < 4; i++) { a[2 * i] = q[i].x; a[2 * i + 1] = q[i].y; }

    // stage negated rows, chunk-major (conflict-free: lane-consecutive b1)
    const unsigned long long SGN = 0x8000000080000000ULL;
#pragma unroll
    for (int i = 0; i < 4; i++)
        sm2[i][b1] = make_ulonglong2(a[2 * i] ^ SGN, a[2 * i + 1] ^ SGN);
    __syncthreads();

    const unsigned long long MSK = 0x7FFFFFFF7FFFFFFFULL;
    float* ob = out + IN_F + o;
    float tot = 0.0f;

    auto body = [&](int t) {
        const int b2 = (b1 + t) & 255;
        ulonglong2 c0 = sm2[0][b2], c1 = sm2[1][b2];
        unsigned long long d0 = addx2(a[0], c0.x) & MSK;
        unsigned long long d1 = addx2(a[1], c0.y) & MSK;
        unsigned long long d2 = addx2(a[2], c1.x) & MSK;
        unsigned long long d3 = addx2(a[3], c1.y) & MSK;
        unsigned long long f  = addx2(addx2(d0, d1), addx2(d2, d3));
        uint32_t flo, fhi;
        asm("mov.b64 {%0,%1}, %2;" : "=r"(flo), "=r"(fhi) : "l"(f));
        float s8 = __uint_as_float(flo) + __uint_as_float(fhi);

        if (s8 < THRESH) {               // else contribution is +0 exactly
            ulonglong2 c2 = sm2[2][b2], c3 = sm2[3][b2];
            unsigned long long d4 = addx2(a[4], c2.x) & MSK;
            unsigned long long d5 = addx2(a[5], c2.y) & MSK;
            unsigned long long d6 = addx2(a[6], c3.x) & MSK;
            unsigned long long d7 = addx2(a[7], c3.y) & MSK;
            unsigned long long g  = addx2(addx2(d4, d5), addx2(d6, d7));
            uint32_t glo, ghi;
            asm("mov.b64 {%0,%1}, %2;" : "=r"(glo), "=r"(ghi) : "l"(g));
            float s16 = s8 + __uint_as_float(glo) + __uint_as_float(ghi);
            float e = __expf(-s16);
            tot += e;
            if (e != 0.0f)               // credit the partner side
                atomicAdd(&ob[(size_t)b2 * OUTW], e);
        }
    };

    // s=0: t = 1..64 (64 iters); s=1: t = 65..127 (63 iters) + peel t=128
    const int t0   = 1 + (s << 6);
    const int tend = t0 + 64 - s;
#pragma unroll 4
    for (int t = t0; t < tend; t++) body(t);
    if (s == 1 && b1 < 128) body(128);   // distance-128 pairs, computed once

    if (tot != 0.0f)
        atomicAdd(&ob[(size_t)b1 * OUTW], tot);
}

extern "C" void kernel_launch(void* const* d_in, const int* in_sizes, int n_in,
                              void* d_out, int out_size)
{
    const float* x = (const float*)d_in[0];     // [256][1024]
    const float* t = (const float*)d_in[1];     // [1024][2048]
    float* out = (float*)d_out;                 // [256][1152]

    float* part;
    cudaGetSymbolAddress((void**)&part, d_part);

    dim3 ggrid(NCOL / BN, BB / BM, SPLITS + 1);  // (32, 4, 5)
    gemm_tf32_kernel<<<ggrid, 128>>>(x, t, part, out);
    pair_kernel<<<dim3(OUT_F, 2), 256>>>(part, out);
}